// round 5
// baseline (speedup 1.0000x reference)
#include <cuda_runtime.h>

#define NB   64
#define NS   512
#define NE   300
#define NH   256
#define NG   1024
#define NT   48
#define NH2  512
#define NTOK (NB*NS)

__device__ float g_z[(size_t)2 * NTOK * NG];
__device__ float g_hout[(size_t)NTOK * NH2];
__device__ float g_probs[(size_t)NTOK * NT];
__device__ float g_hcur[2 * 2 * NB * NH];
__device__ int   g_bar[16];
__device__ float g_res[NB];

__device__ __forceinline__ float fast_sig(float x) { return 1.f / (1.f + __expf(-x)); }
__device__ __forceinline__ float fast_tanh(float x) { return 2.f / (1.f + __expf(-2.f * x)) - 1.f; }

__global__ void init_bar_kernel() {
    if (threadIdx.x < 16) g_bar[threadIdx.x] = 0;
}

__global__ void __launch_bounds__(256) input_gemm_kernel(
    const int* __restrict__ tok, const float* __restrict__ emb,
    const float* __restrict__ wf, const float* __restrict__ wb,
    const float* __restrict__ bif, const float* __restrict__ bhf,
    const float* __restrict__ bib, const float* __restrict__ bhb)
{
    __shared__ float As[60 * 68];
    __shared__ float Bs[60 * 68];
    __shared__ int   ids[64];

    int tid = threadIdx.x;
    int tm = blockIdx.x;
    int tn = blockIdx.y;
    int dir = tn >> 4;
    int rbase = (tn & 15) << 6;
    const float* __restrict__ W = dir ? wb : wf;

    if (tid < 64) ids[tid] = tok[tm * 64 + tid];

    float acc[4][4] = {{0.f}};
    int tx = tid & 15, ty = tid >> 4;

    for (int kc = 0; kc < 5; ++kc) {
        int k0 = kc * 60;
        __syncthreads();
#pragma unroll
        for (int l = 0; l < 15; ++l) {
            int idx = tid + l * 256;
            int i = idx / 60;
            int k = idx - i * 60;
            As[k * 68 + i] = emb[(size_t)ids[i] * NE + k0 + k];
            Bs[k * 68 + i] = W[(size_t)(rbase + i) * NE + k0 + k];
        }
        __syncthreads();
#pragma unroll 4
        for (int k = 0; k < 60; ++k) {
            float4 a4 = *(const float4*)(As + k * 68 + ty * 4);
            float4 b4 = *(const float4*)(Bs + k * 68 + tx * 4);
            float av[4] = {a4.x, a4.y, a4.z, a4.w};
            float bv[4] = {b4.x, b4.y, b4.z, b4.w};
#pragma unroll
            for (int ii = 0; ii < 4; ++ii)
#pragma unroll
                for (int jj = 0; jj < 4; ++jj)
                    acc[ii][jj] = fmaf(av[ii], bv[jj], acc[ii][jj]);
        }
    }

    const float* bi = dir ? bib : bif;
    const float* bh = dir ? bhb : bhf;
    int gcol = rbase + tx * 4;
    float bx = bi[gcol + 0] + bh[gcol + 0];
    float by = bi[gcol + 1] + bh[gcol + 1];
    float bz = bi[gcol + 2] + bh[gcol + 2];
    float bw = bi[gcol + 3] + bh[gcol + 3];

#pragma unroll
    for (int ii = 0; ii < 4; ++ii) {
        int n = tm * 64 + ty * 4 + ii;
        float4 v;
        v.x = acc[ii][0] + bx; v.y = acc[ii][1] + by;
        v.z = acc[ii][2] + bz; v.w = acc[ii][3] + bw;
        *(float4*)&g_z[((size_t)dir * NTOK + n) * NG + gcol] = v;
    }
}

__global__ void __launch_bounds__(128) lstm_kernel(
    const float* __restrict__ whhf, const float* __restrict__ whhb)
{
    extern __shared__ float sm[];
    float* Ws = sm;
    float* hs = sm + 32768;

    int bid = blockIdx.x;
    int dir = bid >> 6;
    int bg  = (bid >> 3) & 7;
    int sl  = bid & 7;
    int us  = sl << 5;
    int tid = threadIdx.x;
    int w   = tid >> 5;
    int lane = tid & 31;
    const float* __restrict__ W = dir ? whhb : whhf;

    for (int idx = tid; idx < 32768; idx += 128) {
        int r = idx & 127, k = idx >> 7;
        Ws[idx] = W[(size_t)((r & 3) * NH + us + (r >> 2)) * NH + k];
    }
    for (int i = tid; i < 2048; i += 128) hs[i] = 0.f;
    __syncthreads();

    int b0 = bg * 8 + w * 2, b1 = b0 + 1;
    int u = us + lane;
    int bar = dir * 8 + bg;
    const float* h0p = hs + (w * 2) * NH;
    const float* h1p = h0p + NH;
    const float4* wp = ((const float4*)Ws) + lane;
    volatile int* vb = (volatile int*)g_bar;
    float c0 = 0.f, c1 = 0.f;

    for (int t = 0; t < NS; ++t) {
        int to = dir ? (NS - 1 - t) : t;
        size_t z0 = ((size_t)dir * NTOK + (size_t)b0 * NS + to) * NG + u;
        size_t z1 = ((size_t)dir * NTOK + (size_t)b1 * NS + to) * NG + u;
        float zi0 = g_z[z0], zf0 = g_z[z0 + 256], zg0 = g_z[z0 + 512], zo0 = g_z[z0 + 768];
        float zi1 = g_z[z1], zf1 = g_z[z1 + 256], zg1 = g_z[z1 + 512], zo1 = g_z[z1 + 768];

        float a0 = 0.f, a1 = 0.f, a2 = 0.f, a3 = 0.f;
        float a4 = 0.f, a5 = 0.f, a6 = 0.f, a7 = 0.f;
#pragma unroll 8
        for (int k = 0; k < NH; ++k) {
            float4 w4 = wp[k * 32];
            float h0 = h0p[k], h1 = h1p[k];
            a0 = fmaf(w4.x, h0, a0); a1 = fmaf(w4.y, h0, a1);
            a2 = fmaf(w4.z, h0, a2); a3 = fmaf(w4.w, h0, a3);
            a4 = fmaf(w4.x, h1, a4); a5 = fmaf(w4.y, h1, a5);
            a6 = fmaf(w4.z, h1, a6); a7 = fmaf(w4.w, h1, a7);
        }

        float i0 = fast_sig(zi0 + a0), f0 = fast_sig(zf0 + a1);
        float gg0 = fast_tanh(zg0 + a2), o0 = fast_sig(zo0 + a3);
        c0 = f0 * c0 + i0 * gg0;
        float hn0 = o0 * fast_tanh(c0);
        float i1 = fast_sig(zi1 + a4), f1 = fast_sig(zf1 + a5);
        float gg1 = fast_tanh(zg1 + a6), o1 = fast_sig(zo1 + a7);
        c1 = f1 * c1 + i1 * gg1;
        float hn1 = o1 * fast_tanh(c1);

        int wbuf = t & 1;
        g_hcur[((wbuf * 2 + dir) * NB + b0) * NH + u] = hn0;
        g_hcur[((wbuf * 2 + dir) * NB + b1) * NH + u] = hn1;
        g_hout[((size_t)b0 * NS + to) * NH2 + dir * NH + u] = hn0;
        g_hout[((size_t)b1 * NS + to) * NH2 + dir * NH + u] = hn1;
        __threadfence();
        __syncthreads();
        if (tid == 0) {
            atomicAdd(&g_bar[bar], 1);
            int tgt = 8 * (t + 1);
            while (vb[bar] < tgt) { }
        }
        __syncthreads();
        __threadfence();

        if (t < NS - 1) {
            for (int i = tid; i < 2048; i += 128) {
                hs[i] = __ldcg(&g_hcur[((wbuf * 2 + dir) * NB + bg * 8 + (i >> 8)) * NH + (i & 255)]);
            }
            __syncthreads();
        }
    }
}

__global__ void __launch_bounds__(256) logits_kernel(
    const float* __restrict__ wlin, const float* __restrict__ blin)
{
    extern __shared__ float sm[];
    float* ws  = sm;
    float* hsm = sm + 24624;
    int tid = threadIdx.x;
    size_t n0 = (size_t)blockIdx.x * 16;

    for (int i = tid; i < NT * NH2; i += 256) ws[(i >> 9) * 513 + (i & 511)] = wlin[i];
    for (int i = tid; i < 16 * NH2; i += 256) hsm[i] = g_hout[n0 * NH2 + i];
    __syncthreads();

    int tk = tid >> 4, js = tid & 15;
    const float* hp = hsm + tk * NH2;
    const float* w0 = ws + (js * 3 + 0) * 513;
    const float* w1 = ws + (js * 3 + 1) * 513;
    const float* w2 = ws + (js * 3 + 2) * 513;
    float a0 = 0.f, a1 = 0.f, a2 = 0.f;
#pragma unroll 8
    for (int k = 0; k < NH2; ++k) {
        float h = hp[k];
        a0 = fmaf(w0[k], h, a0);
        a1 = fmaf(w1[k], h, a1);
        a2 = fmaf(w2[k], h, a2);
    }
    a0 += blin[js * 3 + 0]; a1 += blin[js * 3 + 1]; a2 += blin[js * 3 + 2];

    float m = fmaxf(a0, fmaxf(a1, a2));
#pragma unroll
    for (int off = 8; off; off >>= 1) m = fmaxf(m, __shfl_xor_sync(0xffffffffu, m, off, 16));
    float e0 = __expf(a0 - m), e1 = __expf(a1 - m), e2 = __expf(a2 - m);
    float s = e0 + e1 + e2;
#pragma unroll
    for (int off = 8; off; off >>= 1) s += __shfl_xor_sync(0xffffffffu, s, off, 16);
    float inv = 1.f / s;
    size_t pb = (n0 + tk) * NT + js * 3;
    g_probs[pb + 0] = e0 * inv;
    g_probs[pb + 1] = e1 * inv;
    g_probs[pb + 2] = e2 * inv;
}

__global__ void __launch_bounds__(64) crf_kernel(
    const int* __restrict__ labels, const int* __restrict__ seql,
    const float* __restrict__ trans, const float* __restrict__ st,
    const float* __restrict__ et)
{
    __shared__ float tr[NT * NT];
    __shared__ float alpha[NT];
    __shared__ float red[64];
    int b = blockIdx.x, tid = threadIdx.x;

    for (int i = tid; i < NT * NT; i += 64) tr[i] = trans[i];
    int L = seql[b];
    if (tid < NT) alpha[tid] = st[tid] + g_probs[(size_t)b * NS * NT + tid];
    __syncthreads();

    for (int t = 1; t < NS; ++t) {
        float na = 0.f;
        if (tid < NT) {
            float em = g_probs[((size_t)b * NS + t) * NT + tid];
            float m = -1e30f;
#pragma unroll 4
            for (int i = 0; i < NT; ++i) m = fmaxf(m, alpha[i] + tr[i * NT + tid]);
            float s = 0.f;
#pragma unroll 4
            for (int i = 0; i < NT; ++i) s += __expf(alpha[i] + tr[i * NT + tid] - m);
            na = m + __logf(s) + em;
        }
        __syncthreads();
        if (tid < NT && t < L) alpha[tid] = na;
        __syncthreads();
    }

    float loc = 0.f;
    const int* lb = labels + b * NS;
    for (int t = tid; t < NS; t += 64) {
        int tg = lb[t];
        if (t < L) {
            loc += g_probs[((size_t)b * NS + t) * NT + tg];
            if (t >= 1) loc += tr[lb[t - 1] * NT + tg];
        }
    }
    red[tid] = loc;
    __syncthreads();
    if (tid == 0) {
        float score = 0.f;
        for (int i = 0; i < 64; ++i) score += red[i];
        score += st[lb[0]] + et[lb[L - 1]];
        float m = -1e30f;
        for (int j = 0; j < NT; ++j) m = fmaxf(m, alpha[j] + et[j]);
        float s = 0.f;
        for (int j = 0; j < NT; ++j) s += __expf(alpha[j] + et[j] - m);
        float logz = m + __logf(s);
        g_res[b] = score - logz;
    }
}

__global__ void final_kernel(float* __restrict__ out) {
    if (threadIdx.x == 0) {
        float s = 0.f;
        for (int b = 0; b < NB; ++b) s += g_res[b];
        out[0] = -s;
    }
}

extern "C" void kernel_launch(void* const* d_in, const int* in_sizes, int n_in,
                              void* d_out, int out_size)
{
    (void)in_sizes; (void)n_in; (void)out_size;
    const int*   tok    = (const int*)d_in[0];
    const int*   seql   = (const int*)d_in[1];
    const int*   labels = (const int*)d_in[2];
    const float* emb    = (const float*)d_in[3];
    const float* wihf   = (const float*)d_in[4];
    const float* whhf   = (const float*)d_in[5];
    const float* bihf   = (const float*)d_in[6];
    const float* bhhf   = (const float*)d_in[7];
    const float* wihb   = (const float*)d_in[8];
    const float* whhb   = (const float*)d_in[9];
    const float* bihb   = (const float*)d_in[10];
    const float* bhhb   = (const float*)d_in[11];
    const float* wlin   = (const float*)d_in[12];
    const float* blin   = (const float*)d_in[13];
    const float* trans  = (const float*)d_in[14];
    const float* st     = (const float*)d_in[15];
    const float* et     = (const float*)d_in[16];
    float* out = (float*)d_out;

    cudaFuncSetAttribute(lstm_kernel,   cudaFuncAttributeMaxDynamicSharedMemorySize, 139264);
    cudaFuncSetAttribute(logits_kernel, cudaFuncAttributeMaxDynamicSharedMemorySize, 131264);

    dim3 g1(512, 32);
    input_gemm_kernel<<<g1, 256>>>(tok, emb, wihf, wihb, bihf, bhhf, bihb, bhhb);
    init_bar_kernel<<<1, 32>>>();
    lstm_kernel<<<128, 128, 139264>>>(whhf, whhb);
    logits_kernel<<<2048, 256, 131264>>>(wlin, blin);
    crf_kernel<<<64, 64>>>(labels, seql, trans, st, et);
    final_kernel<<<1, 32>>>(out);
}